// round 11
// baseline (speedup 1.0000x reference)
#include <cuda_runtime.h>
#include <cuda_fp16.h>
#include <math.h>
#include <stdint.h>

#define BATCH 8
#define T 2048
#define E 1024
#define H 64
#define M_TOTAL (BATCH * T)   // 16384

// Scratch (fp16). Static device arrays: allocation-guard safe.
__device__ __half g_Q[M_TOTAL * H];     // [m][h], pre-scaled 0.125*log2e
__device__ __half g_K[M_TOTAL * H];     // [m][h]
__device__ __half g_Vt[BATCH * H * T];  // [b][h][t]  (transposed)

// ---------------------------------------------------------------------------
// helpers
// ---------------------------------------------------------------------------
__device__ __forceinline__ float ex2(float x) {
    float r;
    asm("ex2.approx.f32 %0, %1;" : "=f"(r) : "f"(x));
    return r;
}
__device__ __forceinline__ uint32_t pack2h(float lo, float hi) {
    __half2 h = __floats2half2_rn(lo, hi);
    return *reinterpret_cast<uint32_t*>(&h);
}
__device__ __forceinline__ void mma16(float* c,
                                      uint32_t a0, uint32_t a1, uint32_t a2, uint32_t a3,
                                      uint32_t b0, uint32_t b1) {
    asm("mma.sync.aligned.m16n8k16.row.col.f32.f16.f16.f32 "
        "{%0,%1,%2,%3},{%4,%5,%6,%7},{%8,%9},{%0,%1,%2,%3};"
        : "+f"(c[0]), "+f"(c[1]), "+f"(c[2]), "+f"(c[3])
        : "r"(a0), "r"(a1), "r"(a2), "r"(a3), "r"(b0), "r"(b1));
}
__device__ __forceinline__ void ldm_x4(uint32_t& r0, uint32_t& r1,
                                       uint32_t& r2, uint32_t& r3, uint32_t a) {
    asm volatile("ldmatrix.sync.aligned.m8n8.x4.shared.b16 {%0,%1,%2,%3}, [%4];"
                 : "=r"(r0), "=r"(r1), "=r"(r2), "=r"(r3) : "r"(a));
}
__device__ __forceinline__ void ldm_x4_t(uint32_t& r0, uint32_t& r1,
                                         uint32_t& r2, uint32_t& r3, uint32_t a) {
    asm volatile("ldmatrix.sync.aligned.m8n8.x4.trans.shared.b16 {%0,%1,%2,%3}, [%4];"
                 : "=r"(r0), "=r"(r1), "=r"(r2), "=r"(r3) : "r"(a));
}
__device__ __forceinline__ void cpa16(uint32_t saddr, const void* gptr) {
    asm volatile("cp.async.cg.shared.global [%0], [%1], 16;"
                 :: "r"(saddr), "l"(gptr));
}
#define CP_COMMIT() asm volatile("cp.async.commit_group;")
#define CP_WAIT0()  asm volatile("cp.async.wait_group 0;")

// ---------------------------------------------------------------------------
// Fused QKV projection, fp16 MMA.  X AND W both register-staged from gmem
// (fp32), converted to fp16 on smem store.  W kept in [k][n] order and its
// B-fragments loaded with ldmatrix.x4.trans (no transpose kernel needed).
// CTA 128(M) x 192(N), 8 warps as 2M x 4N (warp 64m x 48n), k-step 32.
// Xs stride 40 halfs; Ws stride 200 halfs (row step = 100 words = 4 banks,
// conflict-free trans-ldmatrix phases).
// ---------------------------------------------------------------------------
#define XSH 40
#define WSN 200
#define PROJ_SMEM_BYTES ((2 * 128 * XSH + 2 * 32 * WSN) * 2)   // 46080

__global__ __launch_bounds__(256, 1) void proj_kernel(
    const float* __restrict__ X,
    const float* __restrict__ Wq,
    const float* __restrict__ Wk,
    const float* __restrict__ Wv)
{
    extern __shared__ __half psm[];
    __half* Xs = psm;                        // [2][128*40]
    __half* Ws = psm + 2 * 128 * XSH;        // [2][32*200]  ([k][n])
    const uint32_t xs_base = (uint32_t)__cvta_generic_to_shared(Xs);
    const uint32_t ws_base = (uint32_t)__cvta_generic_to_shared(Ws);

    const int m0   = blockIdx.x * 128;
    const int tid  = threadIdx.x;
    const int w    = tid >> 5;
    const int lane = tid & 31;
    const int g    = lane >> 2;
    const int t    = lane & 3;
    const int wm   = (w >> 2) * 64;          // 0,64
    const int wn   = (w & 3) * 48;           // 0,48,96,144
    const int lr   = lane & 7;
    const int lt8  = ((lane >> 3) & 1) * 8;  // A-frag row-half select
    const int lc8  = (lane >> 4) * 8;        // A-frag col-half select
    // trans B-frag lane mapping: tile = lane>>3 -> row-half (tile&1), col-half (tile>>1)
    const int wrow = lr + ((lane >> 3) & 1) * 8;
    const int wcol = (lane >> 4) * 8;

    float4 xa[4], wa[6];
    auto loadX = [&](int k0) {
#pragma unroll
        for (int i = 0; i < 4; i++) {
            int idx = tid + i * 256;
            int row = idx >> 3;
            int c4  = (idx & 7) << 2;
            xa[i] = *reinterpret_cast<const float4*>(
                X + (size_t)(m0 + row) * E + k0 + c4);
        }
    };
    auto loadW = [&](int k0) {
#pragma unroll
        for (int i = 0; i < 6; i++) {
            int idx = tid + i * 256;             // 0..1535
            int kr  = idx / 48;                  // 0..31
            int c4  = (idx % 48) * 4;            // 0..188
            const float* src = (c4 < 64)  ? (Wq + (size_t)(k0 + kr) * H + c4)
                             : (c4 < 128) ? (Wk + (size_t)(k0 + kr) * H + (c4 - 64))
                                          : (Wv + (size_t)(k0 + kr) * H + (c4 - 128));
            wa[i] = *reinterpret_cast<const float4*>(src);
        }
    };
    auto storeTiles = [&](int buf) {
#pragma unroll
        for (int i = 0; i < 4; i++) {
            int idx = tid + i * 256;
            int row = idx >> 3;
            int c4  = (idx & 7) << 2;
            *reinterpret_cast<uint2*>(&Xs[buf * 128 * XSH + row * XSH + c4]) =
                make_uint2(pack2h(xa[i].x, xa[i].y), pack2h(xa[i].z, xa[i].w));
        }
#pragma unroll
        for (int i = 0; i < 6; i++) {
            int idx = tid + i * 256;
            int kr  = idx / 48;
            int c4  = (idx % 48) * 4;
            *reinterpret_cast<uint2*>(&Ws[buf * 32 * WSN + kr * WSN + c4]) =
                make_uint2(pack2h(wa[i].x, wa[i].y), pack2h(wa[i].z, wa[i].w));
        }
    };

    float acc[4][6][4] = {};

    loadX(0);
    loadW(0);
    for (int ks = 0; ks < 32; ks++) {
        storeTiles(ks & 1);
        __syncthreads();
        if (ks < 31) { loadX((ks + 1) * 32); loadW((ks + 1) * 32); }

        const uint32_t xb = xs_base + (uint32_t)((ks & 1) * 128 * XSH) * 2;
        const uint32_t wb = ws_base + (uint32_t)((ks & 1) * 32 * WSN) * 2;

#pragma unroll
        for (int kc = 0; kc < 2; kc++) {
            // W B-fragments via trans ldmatrix: one x4 -> (b0,b1) for 2 nt
            uint32_t bw[3][4];
#pragma unroll
            for (int nt2 = 0; nt2 < 3; nt2++) {
                uint32_t wa32 = wb + (uint32_t)(
                    (kc * 16 + wrow) * WSN + wn + nt2 * 16 + wcol) * 2;
                ldm_x4_t(bw[nt2][0], bw[nt2][1], bw[nt2][2], bw[nt2][3], wa32);
            }
            uint32_t a[4][4];
#pragma unroll
            for (int mt = 0; mt < 4; mt++) {
                uint32_t xaddr = xb + (uint32_t)(
                    (wm + mt * 16 + lt8 + lr) * XSH + kc * 16 + lc8) * 2;
                ldm_x4(a[mt][0], a[mt][1], a[mt][2], a[mt][3], xaddr);
            }
#pragma unroll
            for (int nt = 0; nt < 6; nt++) {
                uint32_t b0 = bw[nt >> 1][(nt & 1) * 2 + 0];
                uint32_t b1 = bw[nt >> 1][(nt & 1) * 2 + 1];
#pragma unroll
                for (int mt = 0; mt < 4; mt++)
                    mma16(acc[mt][nt], a[mt][0], a[mt][1], a[mt][2], a[mt][3], b0, b1);
            }
        }
    }

    // Epilogue: fp16 stores (Q pre-scaled; V transposed)
    const float QSCALE = 0.125f * 1.4426950408889634f;
#pragma unroll
    for (int mt = 0; mt < 4; mt++) {
        int r0 = m0 + wm + mt * 16 + g;
#pragma unroll
        for (int nt = 0; nt < 6; nt++) {
            int c = wn + nt * 8 + 2 * t;
            if (c < 64) {
                *reinterpret_cast<uint32_t*>(&g_Q[(size_t)r0 * H + c]) =
                    pack2h(acc[mt][nt][0] * QSCALE, acc[mt][nt][1] * QSCALE);
                *reinterpret_cast<uint32_t*>(&g_Q[(size_t)(r0 + 8) * H + c]) =
                    pack2h(acc[mt][nt][2] * QSCALE, acc[mt][nt][3] * QSCALE);
            } else if (c < 128) {
                int cc = c - 64;
                *reinterpret_cast<uint32_t*>(&g_K[(size_t)r0 * H + cc]) =
                    pack2h(acc[mt][nt][0], acc[mt][nt][1]);
                *reinterpret_cast<uint32_t*>(&g_K[(size_t)(r0 + 8) * H + cc]) =
                    pack2h(acc[mt][nt][2], acc[mt][nt][3]);
            } else {
                int h = c - 128;
                int bb = r0 / T, tk = r0 % T;
                __half* vb = g_Vt + (size_t)bb * H * T;
                vb[(size_t)h * T + tk]           = __float2half_rn(acc[mt][nt][0]);
                vb[(size_t)(h + 1) * T + tk]     = __float2half_rn(acc[mt][nt][1]);
                vb[(size_t)h * T + tk + 8]       = __float2half_rn(acc[mt][nt][2]);
                vb[(size_t)(h + 1) * T + tk + 8] = __float2half_rn(acc[mt][nt][3]);
            }
        }
    }
}

// ---------------------------------------------------------------------------
// Flash attention (causal), fp16 MMA, 2x2 warp split, P in registers.
// BK=128: one cp.async wait + one syncthreads per 128 keys (two 64-key
// halves computed back-to-back); fully-masked 64-key sub-blocks skipped.
// K [key][h] stride 72; V [h][key] stride 136 (both conflict-free).
// ---------------------------------------------------------------------------
#define KSN 72
#define VSN 136
#define ATTN_SMEM_BYTES ((2 * 128 * KSN + 2 * 64 * VSN) * 2)   // 71680

__global__ __launch_bounds__(128, 2) void attn_kernel(float* __restrict__ out)
{
    extern __shared__ __half hsm[];
    __half* Ks = hsm;                          // [2][128 keys x 72]
    __half* Vs = Ks + 2 * 128 * KSN;           // [2][64 h x 136]
    const uint32_t ks_base = (uint32_t)__cvta_generic_to_shared(Ks);
    const uint32_t vs_base = (uint32_t)__cvta_generic_to_shared(Vs);

    // balanced (b, qt) schedule
    const int cidx = blockIdx.x;
    int s;
    if (cidx < 108)       s = 40 + cidx;
    else if (cidx < 148)  s = cidx - 108;
    else                  s = 403 - cidx;
    const int qt = 31 - (s >> 3);
    const int b  = s & 7;
    const int q0 = qt * 64;

    const int tid  = threadIdx.x;
    const int w    = tid >> 5;
    const int lane = tid & 31;
    const int g    = lane >> 2;
    const int t    = lane & 3;
    const int qw   = w >> 1;
    const int kw   = w & 1;
    const int lr   = lane & 7;
    const int lt   = lane >> 3;

    const __half* __restrict__ Qg = g_Q + ((size_t)b * T + q0) * H;
    const __half* __restrict__ Kg = g_K + (size_t)b * T * H;
    const __half* __restrict__ Vg = g_Vt + (size_t)b * H * T;

    auto issueKV = [&](int buf, int k0) {
#pragma unroll
        for (int i = 0; i < 8; i++) {          // K: 128 rows x 64 halfs
            int idx = tid + i * 128;           // 0..1023
            int row = idx >> 3;                // 0..127
            int c8  = (idx & 7) << 3;
            cpa16(ks_base + (uint32_t)(buf * 128 * KSN + row * KSN + c8) * 2,
                  Kg + (size_t)(k0 + row) * H + c8);
        }
#pragma unroll
        for (int i = 0; i < 8; i++) {          // V: 64 rows x 128 halfs
            int idx = tid + i * 128;
            int row = idx >> 4;                // 0..63
            int c8  = (idx & 15) << 3;         // 0..120
            cpa16(vs_base + (uint32_t)(buf * 64 * VSN + row * VSN + c8) * 2,
                  Vg + (size_t)row * T + k0 + c8);
        }
        CP_COMMIT();
    };

    const int nkt = qt / 2 + 1;
    issueKV(0, 0);

    // Q A-fragments
    uint32_t qa[2][4][4];
#pragma unroll
    for (int qh = 0; qh < 2; qh++) {
        int r = qw * 32 + qh * 16 + g;
#pragma unroll
        for (int kc = 0; kc < 4; kc++) {
            int c = kc * 16 + 2 * t;
            qa[qh][kc][0] = *reinterpret_cast<const uint32_t*>(&Qg[(size_t)r * H + c]);
            qa[qh][kc][1] = *reinterpret_cast<const uint32_t*>(&Qg[(size_t)(r + 8) * H + c]);
            qa[qh][kc][2] = *reinterpret_cast<const uint32_t*>(&Qg[(size_t)r * H + c + 8]);
            qa[qh][kc][3] = *reinterpret_cast<const uint32_t*>(&Qg[(size_t)(r + 8) * H + c + 8]);
        }
    }

    float lacc[2][2] = {};
    float accO[2][8][4] = {};

    for (int kt = 0; kt < nkt; kt++) {
        CP_WAIT0();
        __syncthreads();
        if (kt + 1 < nkt) issueKV((kt + 1) & 1, (kt + 1) * 128);

        const uint32_t kbuf = (uint32_t)((kt & 1) * 128 * KSN) * 2;
        const uint32_t vbuf = (uint32_t)((kt & 1) * 64 * VSN) * 2;

#pragma unroll
        for (int hb = 0; hb < 2; hb++) {
            const int kbase   = kt * 128 + hb * 64;          // global key base
            const int kwstart = kbase + kw * 32;             // this warp's first key
            if (kwstart > q0 + qw * 32 + 31) continue;       // fully masked
            const bool needmask = (kwstart + 31 > q0 + qw * 32);
            const int srow = hb * 64 + kw * 32;              // smem key offset

            // ---- S = Q @ K^T ----
            float sv[2][4][4] = {};
#pragma unroll
            for (int hc = 0; hc < 2; hc++) {
#pragma unroll
                for (int nt = 0; nt < 4; nt++) {
                    uint32_t kb0, kb1, kb2, kb3;
                    uint32_t ka = ks_base + kbuf +
                        (uint32_t)((srow + nt * 8 + lr) * KSN + hc * 32 + lt * 8) * 2;
                    ldm_x4(kb0, kb1, kb2, kb3, ka);
#pragma unroll
                    for (int qh = 0; qh < 2; qh++) {
                        mma16(sv[qh][nt], qa[qh][2*hc][0], qa[qh][2*hc][1],
                              qa[qh][2*hc][2], qa[qh][2*hc][3], kb0, kb1);
                        mma16(sv[qh][nt], qa[qh][2*hc+1][0], qa[qh][2*hc+1][1],
                              qa[qh][2*hc+1][2], qa[qh][2*hc+1][3], kb2, kb3);
                    }
                }
            }

            // causal mask (global indices)
            if (needmask) {
#pragma unroll
                for (int qh = 0; qh < 2; qh++) {
                    int r0 = q0 + qw * 32 + qh * 16 + g;
                    int r1 = r0 + 8;
#pragma unroll
                    for (int nt = 0; nt < 4; nt++) {
                        int cc = kwstart + nt * 8 + 2 * t;
                        if (cc     > r0) sv[qh][nt][0] = -1e30f;
                        if (cc + 1 > r0) sv[qh][nt][1] = -1e30f;
                        if (cc     > r1) sv[qh][nt][2] = -1e30f;
                        if (cc + 1 > r1) sv[qh][nt][3] = -1e30f;
                    }
                }
            }

            // ---- p = 2^sv; accumulate l; repack C-frag -> P A-frag ----
            uint32_t pa[2][2][4];
#pragma unroll
            for (int qh = 0; qh < 2; qh++) {
#pragma unroll
                for (int nt = 0; nt < 4; nt++) {
                    float p0 = ex2(sv[qh][nt][0]);
                    float p1 = ex2(sv[qh][nt][1]);
                    float p2 = ex2(sv[qh][nt][2]);
                    float p3 = ex2(sv[qh][nt][3]);
                    lacc[qh][0] += p0 + p1;
                    lacc[qh][1] += p2 + p3;
                    pa[qh][nt >> 1][(nt & 1) * 2 + 0] = pack2h(p0, p1);
                    pa[qh][nt >> 1][(nt & 1) * 2 + 1] = pack2h(p2, p3);
                }
            }

            // ---- O += P @ V ----
#pragma unroll
            for (int nh = 0; nh < 8; nh++) {
                uint32_t vb0, vb1, vb2, vb3;
                uint32_t va = vs_base + vbuf +
                    (uint32_t)((nh * 8 + lr) * VSN + srow + lt * 8) * 2;
                ldm_x4(vb0, vb1, vb2, vb3, va);
#pragma unroll
                for (int qh = 0; qh < 2; qh++) {
                    mma16(accO[qh][nh], pa[qh][0][0], pa[qh][0][1],
                          pa[qh][0][2], pa[qh][0][3], vb0, vb1);
                    mma16(accO[qh][nh], pa[qh][1][0], pa[qh][1][1],
                          pa[qh][1][2], pa[qh][1][3], vb2, vb3);
                }
            }
        }
    }

    // ---- epilogue: reduce partials across the kw pair, normalize, store ----
#pragma unroll
    for (int qh = 0; qh < 2; qh++)
#pragma unroll
        for (int i = 0; i < 2; i++) {
            lacc[qh][i] += __shfl_xor_sync(0xffffffffu, lacc[qh][i], 1);
            lacc[qh][i] += __shfl_xor_sync(0xffffffffu, lacc[qh][i], 2);
        }

    __syncthreads();   // all tiles done; smem reusable as f32 staging
    float* Ored = (float*)hsm;                       // [64 q][64 h]
    float* Lred = (float*)hsm + 64 * 64;             // [64 q]

    if (kw == 1) {
#pragma unroll
        for (int qh = 0; qh < 2; qh++) {
            int r = qw * 32 + qh * 16 + g;
#pragma unroll
            for (int nh = 0; nh < 8; nh++) {
                int c = nh * 8 + 2 * t;
                *reinterpret_cast<float2*>(&Ored[(size_t)r * 64 + c]) =
                    make_float2(accO[qh][nh][0], accO[qh][nh][1]);
                *reinterpret_cast<float2*>(&Ored[(size_t)(r + 8) * 64 + c]) =
                    make_float2(accO[qh][nh][2], accO[qh][nh][3]);
            }
            if (t == 0) {
                Lred[r]     = lacc[qh][0];
                Lred[r + 8] = lacc[qh][1];
            }
        }
    }
    __syncthreads();

    if (kw == 0) {
#pragma unroll
        for (int qh = 0; qh < 2; qh++) {
            int rl = qw * 32 + qh * 16 + g;
            float i0 = 1.f / (lacc[qh][0] + Lred[rl]);
            float i1 = 1.f / (lacc[qh][1] + Lred[rl + 8]);
            int r = q0 + rl;
#pragma unroll
            for (int nh = 0; nh < 8; nh++) {
                int c = nh * 8 + 2 * t;
                float2 o0 = *reinterpret_cast<const float2*>(&Ored[(size_t)rl * 64 + c]);
                float2 o1 = *reinterpret_cast<const float2*>(&Ored[(size_t)(rl + 8) * 64 + c]);
                float* o = out + ((size_t)b * T + r) * H + c;
                *reinterpret_cast<float2*>(o) =
                    make_float2((accO[qh][nh][0] + o0.x) * i0,
                                (accO[qh][nh][1] + o0.y) * i0);
                *reinterpret_cast<float2*>(o + 8 * H) =
                    make_float2((accO[qh][nh][2] + o1.x) * i1,
                                (accO[qh][nh][3] + o1.y) * i1);
            }
        }
    }
}

// ---------------------------------------------------------------------------
extern "C" void kernel_launch(void* const* d_in, const int* in_sizes, int n_in,
                              void* d_out, int out_size)
{
    const float* X  = (const float*)d_in[0];
    const float* Wq = (const float*)d_in[1];
    const float* Wk = (const float*)d_in[2];
    const float* Wv = (const float*)d_in[3];
    float* out = (float*)d_out;

    // 1) Fused QKV projection (W converted inline; no separate cvt kernel)
    cudaFuncSetAttribute(proj_kernel,
                         cudaFuncAttributeMaxDynamicSharedMemorySize,
                         PROJ_SMEM_BYTES);
    proj_kernel<<<M_TOTAL / 128, 256, PROJ_SMEM_BYTES>>>(X, Wq, Wk, Wv);

    // 2) Causal flash attention (BK=128)
    cudaFuncSetAttribute(attn_kernel,
                         cudaFuncAttributeMaxDynamicSharedMemorySize,
                         ATTN_SMEM_BYTES);
    attn_kernel<<<(T / 64) * BATCH, 128, ATTN_SMEM_BYTES>>>(out);
}

// round 12
// speedup vs baseline: 1.0211x; 1.0211x over previous
#include <cuda_runtime.h>
#include <cuda_fp16.h>
#include <math.h>
#include <stdint.h>

#define BATCH 8
#define T 2048
#define E 1024
#define H 64
#define M_TOTAL (BATCH * T)   // 16384

// Scratch (fp16). Static device arrays: allocation-guard safe.
__device__ __half g_Q[M_TOTAL * H];     // [m][h], pre-scaled 0.125*log2e
__device__ __half g_K[M_TOTAL * H];     // [m][h]
__device__ __half g_Vt[BATCH * H * T];  // [b][h][t]  (transposed)
__device__ __half g_Wt[192 * E];        // [n][k]     (Wq|Wk|Wv transposed)

// ---------------------------------------------------------------------------
// helpers
// ---------------------------------------------------------------------------
__device__ __forceinline__ uint32_t pack2h(float lo, float hi) {
    __half2 h = __floats2half2_rn(lo, hi);
    return *reinterpret_cast<uint32_t*>(&h);
}
__device__ __forceinline__ uint32_t ex2h2(uint32_t x) {
    uint32_t r;
    asm("ex2.approx.f16x2 %0, %1;" : "=r"(r) : "r"(x));
    return r;
}
__device__ __forceinline__ void mma16(float* c,
                                      uint32_t a0, uint32_t a1, uint32_t a2, uint32_t a3,
                                      uint32_t b0, uint32_t b1) {
    asm("mma.sync.aligned.m16n8k16.row.col.f32.f16.f16.f32 "
        "{%0,%1,%2,%3},{%4,%5,%6,%7},{%8,%9},{%0,%1,%2,%3};"
        : "+f"(c[0]), "+f"(c[1]), "+f"(c[2]), "+f"(c[3])
        : "r"(a0), "r"(a1), "r"(a2), "r"(a3), "r"(b0), "r"(b1));
}
__device__ __forceinline__ void ldm_x4(uint32_t& r0, uint32_t& r1,
                                       uint32_t& r2, uint32_t& r3, uint32_t a) {
    asm volatile("ldmatrix.sync.aligned.m8n8.x4.shared.b16 {%0,%1,%2,%3}, [%4];"
                 : "=r"(r0), "=r"(r1), "=r"(r2), "=r"(r3) : "r"(a));
}
__device__ __forceinline__ void cpa16(uint32_t saddr, const void* gptr) {
    asm volatile("cp.async.cg.shared.global [%0], [%1], 16;"
                 :: "r"(saddr), "l"(gptr));
}
#define CP_COMMIT() asm volatile("cp.async.commit_group;")
#define CP_WAIT0()  asm volatile("cp.async.wait_group 0;")

// ---------------------------------------------------------------------------
// W pre-convert, coalesced 64x64 tile transpose via smem.  (R10 version)
// ---------------------------------------------------------------------------
__global__ void cvtW_kernel(const float* __restrict__ Wq,
                            const float* __restrict__ Wk,
                            const float* __restrict__ Wv)
{
    __shared__ __half ts[64][72];
    const int k0 = blockIdx.x * 64;
    const int n0 = blockIdx.y * 64;
    const float* __restrict__ src =
        (blockIdx.y == 0) ? Wq : (blockIdx.y == 1) ? Wk : Wv;
    const int tid = threadIdx.x;

#pragma unroll
    for (int i = 0; i < 4; i++) {
        int idx  = tid + i * 256;
        int krow = idx >> 4;
        int c4   = (idx & 15) << 2;
        float4 v = *reinterpret_cast<const float4*>(
            src + (size_t)(k0 + krow) * H + c4);
        ts[c4 + 0][krow] = __float2half_rn(v.x);
        ts[c4 + 1][krow] = __float2half_rn(v.y);
        ts[c4 + 2][krow] = __float2half_rn(v.z);
        ts[c4 + 3][krow] = __float2half_rn(v.w);
    }
    __syncthreads();
#pragma unroll
    for (int i = 0; i < 4; i++) {
        int odx = tid + i * 256;
        int n   = odx >> 4;
        int k4  = (odx & 15) << 2;
        *reinterpret_cast<uint2*>(&g_Wt[(size_t)(n0 + n) * E + k0 + k4]) =
            *reinterpret_cast<const uint2*>(&ts[n][k4]);
    }
}

// ---------------------------------------------------------------------------
// Fused QKV projection (R10 version): fp16 MMA, X register-staged fp16,
// W (pre-converted) via cp.async, fragments via ldmatrix.x4.
// CTA 128(M) x 192(N), 8 warps as 2M x 4N (warp 64m x 48n), k-step 32.
// ---------------------------------------------------------------------------
#define XSH 40
#define WSH 40
#define PROJ_SMEM_BYTES ((2 * 128 * XSH + 2 * 192 * WSH) * 2)   // 51200

__global__ __launch_bounds__(256, 1) void proj_kernel(const float* __restrict__ X)
{
    extern __shared__ __half psm[];
    __half* Xs = psm;                        // [2][128*40]
    __half* Ws = psm + 2 * 128 * XSH;        // [2][192*40]
    const uint32_t xs_base = (uint32_t)__cvta_generic_to_shared(Xs);
    const uint32_t ws_base = (uint32_t)__cvta_generic_to_shared(Ws);

    const int m0   = blockIdx.x * 128;
    const int tid  = threadIdx.x;
    const int w    = tid >> 5;
    const int lane = tid & 31;
    const int g    = lane >> 2;
    const int t    = lane & 3;
    const int wm   = (w >> 2) * 64;          // 0,64
    const int wn   = (w & 3) * 48;           // 0,48,96,144
    const int lr   = lane & 7;
    const int lt8  = ((lane >> 3) & 1) * 8;
    const int lc8  = (lane >> 4) * 8;

    float4 xa[4];
    auto loadX = [&](int k0) {
#pragma unroll
        for (int i = 0; i < 4; i++) {
            int idx = tid + i * 256;
            int row = idx >> 3;
            int c4  = (idx & 7) << 2;
            xa[i] = *reinterpret_cast<const float4*>(
                X + (size_t)(m0 + row) * E + k0 + c4);
        }
    };
    auto storeX = [&](int buf) {
#pragma unroll
        for (int i = 0; i < 4; i++) {
            int idx = tid + i * 256;
            int row = idx >> 3;
            int c4  = (idx & 7) << 2;
            *reinterpret_cast<uint2*>(&Xs[buf * 128 * XSH + row * XSH + c4]) =
                make_uint2(pack2h(xa[i].x, xa[i].y), pack2h(xa[i].z, xa[i].w));
        }
    };
    auto issueW = [&](int buf, int k0) {
#pragma unroll
        for (int i = 0; i < 3; i++) {
            int idx = tid + i * 256;
            int n   = idx >> 2;
            int c8  = (idx & 3) << 3;
            cpa16(ws_base + (uint32_t)(buf * 192 * WSH + n * WSH + c8) * 2,
                  g_Wt + (size_t)n * E + k0 + c8);
        }
        CP_COMMIT();
    };

    float acc[4][6][4] = {};

    loadX(0);
    issueW(0, 0);
    for (int ks = 0; ks < 32; ks++) {
        storeX(ks & 1);
        CP_WAIT0();
        __syncthreads();
        if (ks < 31) { loadX((ks + 1) * 32); issueW((ks + 1) & 1, (ks + 1) * 32); }

        const uint32_t xb = xs_base + (uint32_t)((ks & 1) * 128 * XSH) * 2;
        const uint32_t wb = ws_base + (uint32_t)((ks & 1) * 192 * WSH) * 2;

        uint32_t bw[6][4];
#pragma unroll
        for (int nt = 0; nt < 6; nt++) {
            uint32_t wa = wb + (uint32_t)((wn + nt * 8 + lr) * WSH + (lane >> 3) * 8) * 2;
            ldm_x4(bw[nt][0], bw[nt][1], bw[nt][2], bw[nt][3], wa);
        }
#pragma unroll
        for (int kc = 0; kc < 2; kc++) {
            uint32_t a[4][4];
#pragma unroll
            for (int mt = 0; mt < 4; mt++) {
                uint32_t xaddr = xb + (uint32_t)(
                    (wm + mt * 16 + lt8 + lr) * XSH + kc * 16 + lc8) * 2;
                ldm_x4(a[mt][0], a[mt][1], a[mt][2], a[mt][3], xaddr);
            }
#pragma unroll
            for (int nt = 0; nt < 6; nt++) {
                uint32_t b0 = bw[nt][2 * kc];
                uint32_t b1 = bw[nt][2 * kc + 1];
#pragma unroll
                for (int mt = 0; mt < 4; mt++)
                    mma16(acc[mt][nt], a[mt][0], a[mt][1], a[mt][2], a[mt][3], b0, b1);
            }
        }
    }

    // Epilogue: fp16 stores (Q pre-scaled; V transposed)
    const float QSCALE = 0.125f * 1.4426950408889634f;
#pragma unroll
    for (int mt = 0; mt < 4; mt++) {
        int r0 = m0 + wm + mt * 16 + g;
#pragma unroll
        for (int nt = 0; nt < 6; nt++) {
            int c = wn + nt * 8 + 2 * t;
            if (c < 64) {
                *reinterpret_cast<uint32_t*>(&g_Q[(size_t)r0 * H + c]) =
                    pack2h(acc[mt][nt][0] * QSCALE, acc[mt][nt][1] * QSCALE);
                *reinterpret_cast<uint32_t*>(&g_Q[(size_t)(r0 + 8) * H + c]) =
                    pack2h(acc[mt][nt][2] * QSCALE, acc[mt][nt][3] * QSCALE);
            } else if (c < 128) {
                int cc = c - 64;
                *reinterpret_cast<uint32_t*>(&g_K[(size_t)r0 * H + cc]) =
                    pack2h(acc[mt][nt][0], acc[mt][nt][1]);
                *reinterpret_cast<uint32_t*>(&g_K[(size_t)(r0 + 8) * H + cc]) =
                    pack2h(acc[mt][nt][2], acc[mt][nt][3]);
            } else {
                int h = c - 128;
                int bb = r0 / T, tk = r0 % T;
                __half* vb = g_Vt + (size_t)bb * H * T;
                vb[(size_t)h * T + tk]           = __float2half_rn(acc[mt][nt][0]);
                vb[(size_t)(h + 1) * T + tk]     = __float2half_rn(acc[mt][nt][1]);
                vb[(size_t)h * T + tk + 8]       = __float2half_rn(acc[mt][nt][2]);
                vb[(size_t)(h + 1) * T + tk + 8] = __float2half_rn(acc[mt][nt][3]);
            }
        }
    }
}

// ---------------------------------------------------------------------------
// Flash attention (causal), fp16 MMA, 2x2 warp split, BK=128, P in regs.
// NEW: softmax via ex2.approx.f16x2 (half the MUFU ops; result IS the P
// fragment) and l computed by a static ones-column in V (row 64 = 1,
// rows 65-71 = 0): l falls out of the PV MMA in fp32, no scalar FADDs.
// ---------------------------------------------------------------------------
#define KSN 72
#define VSN 136
#define VROWS 72
#define ATTN_SMEM_BYTES ((2 * 128 * KSN + 2 * VROWS * VSN) * 2)   // 76032

__global__ __launch_bounds__(128, 2) void attn_kernel(float* __restrict__ out)
{
    extern __shared__ __half hsm[];
    __half* Ks = hsm;                          // [2][128 keys x 72]
    __half* Vs = Ks + 2 * 128 * KSN;           // [2][72 h x 136]
    const uint32_t ks_base = (uint32_t)__cvta_generic_to_shared(Ks);
    const uint32_t vs_base = (uint32_t)__cvta_generic_to_shared(Vs);

    // balanced (b, qt) schedule
    const int cidx = blockIdx.x;
    int s;
    if (cidx < 108)       s = 40 + cidx;
    else if (cidx < 148)  s = cidx - 108;
    else                  s = 403 - cidx;
    const int qt = 31 - (s >> 3);
    const int b  = s & 7;
    const int q0 = qt * 64;

    const int tid  = threadIdx.x;
    const int w    = tid >> 5;
    const int lane = tid & 31;
    const int g    = lane >> 2;
    const int t    = lane & 3;
    const int qw   = w >> 1;
    const int kw   = w & 1;
    const int lr   = lane & 7;
    const int lt   = lane >> 3;

    const __half* __restrict__ Qg = g_Q + ((size_t)b * T + q0) * H;
    const __half* __restrict__ Kg = g_K + (size_t)b * T * H;
    const __half* __restrict__ Vg = g_Vt + (size_t)b * H * T;

    auto issueKV = [&](int buf, int k0) {
#pragma unroll
        for (int i = 0; i < 8; i++) {          // K: 128 rows x 64 halfs
            int idx = tid + i * 128;
            int row = idx >> 3;
            int c8  = (idx & 7) << 3;
            cpa16(ks_base + (uint32_t)(buf * 128 * KSN + row * KSN + c8) * 2,
                  Kg + (size_t)(k0 + row) * H + c8);
        }
#pragma unroll
        for (int i = 0; i < 8; i++) {          // V: rows 0-63 only
            int idx = tid + i * 128;
            int row = idx >> 4;
            int c8  = (idx & 15) << 3;
            cpa16(vs_base + (uint32_t)(buf * VROWS * VSN + row * VSN + c8) * 2,
                  Vg + (size_t)row * T + k0 + c8);
        }
        CP_COMMIT();
    };

    const int nkt = qt / 2 + 1;
    issueKV(0, 0);

    // Init V ones-column rows (64 = 1.0, 65-71 = 0) in both buffers.
    // cp.async never touches rows >= 64, so this persists across tiles.
    {
        const __half one  = __float2half_rn(1.0f);
        const __half zero = __float2half_rn(0.0f);
        for (int idx = tid; idx < 2 * 8 * VSN; idx += 128) {
            int buf = idx / (8 * VSN);
            int rem = idx % (8 * VSN);
            int row = 64 + rem / VSN;
            int col = rem % VSN;
            Vs[buf * VROWS * VSN + row * VSN + col] = (row == 64) ? one : zero;
        }
    }

    // Q A-fragments
    uint32_t qa[2][4][4];
#pragma unroll
    for (int qh = 0; qh < 2; qh++) {
        int r = qw * 32 + qh * 16 + g;
#pragma unroll
        for (int kc = 0; kc < 4; kc++) {
            int c = kc * 16 + 2 * t;
            qa[qh][kc][0] = *reinterpret_cast<const uint32_t*>(&Qg[(size_t)r * H + c]);
            qa[qh][kc][1] = *reinterpret_cast<const uint32_t*>(&Qg[(size_t)(r + 8) * H + c]);
            qa[qh][kc][2] = *reinterpret_cast<const uint32_t*>(&Qg[(size_t)r * H + c + 8]);
            qa[qh][kc][3] = *reinterpret_cast<const uint32_t*>(&Qg[(size_t)(r + 8) * H + c + 8]);
        }
    }

    float accO[2][9][4] = {};     // [qh][nh 0..7 = O cols, 8 = l column]

    for (int kt = 0; kt < nkt; kt++) {
        CP_WAIT0();
        __syncthreads();
        if (kt + 1 < nkt) issueKV((kt + 1) & 1, (kt + 1) * 128);

        const uint32_t kbuf = (uint32_t)((kt & 1) * 128 * KSN) * 2;
        const uint32_t vbuf = (uint32_t)((kt & 1) * VROWS * VSN) * 2;

#pragma unroll
        for (int hb = 0; hb < 2; hb++) {
            const int kbase   = kt * 128 + hb * 64;
            const int kwstart = kbase + kw * 32;
            if (kwstart > q0 + qw * 32 + 31) continue;       // fully masked
            const bool needmask = (kwstart + 31 > q0 + qw * 32);
            const int srow = hb * 64 + kw * 32;

            // ---- S = Q @ K^T ----
            float sv[2][4][4] = {};
#pragma unroll
            for (int hc = 0; hc < 2; hc++) {
#pragma unroll
                for (int nt = 0; nt < 4; nt++) {
                    uint32_t kb0, kb1, kb2, kb3;
                    uint32_t ka = ks_base + kbuf +
                        (uint32_t)((srow + nt * 8 + lr) * KSN + hc * 32 + lt * 8) * 2;
                    ldm_x4(kb0, kb1, kb2, kb3, ka);
#pragma unroll
                    for (int qh = 0; qh < 2; qh++) {
                        mma16(sv[qh][nt], qa[qh][2*hc][0], qa[qh][2*hc][1],
                              qa[qh][2*hc][2], qa[qh][2*hc][3], kb0, kb1);
                        mma16(sv[qh][nt], qa[qh][2*hc+1][0], qa[qh][2*hc+1][1],
                              qa[qh][2*hc+1][2], qa[qh][2*hc+1][3], kb2, kb3);
                    }
                }
            }

            // causal mask (global indices)
            if (needmask) {
#pragma unroll
                for (int qh = 0; qh < 2; qh++) {
                    int r0 = q0 + qw * 32 + qh * 16 + g;
                    int r1 = r0 + 8;
#pragma unroll
                    for (int nt = 0; nt < 4; nt++) {
                        int cc = kwstart + nt * 8 + 2 * t;
                        if (cc     > r0) sv[qh][nt][0] = -1e30f;
                        if (cc + 1 > r0) sv[qh][nt][1] = -1e30f;
                        if (cc     > r1) sv[qh][nt][2] = -1e30f;
                        if (cc + 1 > r1) sv[qh][nt][3] = -1e30f;
                    }
                }
            }

            // ---- P = 2^S on the fp16 pipe: cvt pair -> ex2.f16x2 = P frag ----
            uint32_t pa[2][2][4];
#pragma unroll
            for (int qh = 0; qh < 2; qh++) {
#pragma unroll
                for (int nt = 0; nt < 4; nt++) {
                    pa[qh][nt >> 1][(nt & 1) * 2 + 0] =
                        ex2h2(pack2h(sv[qh][nt][0], sv[qh][nt][1]));
                    pa[qh][nt >> 1][(nt & 1) * 2 + 1] =
                        ex2h2(pack2h(sv[qh][nt][2], sv[qh][nt][3]));
                }
            }

            // ---- [O | l] += P @ [V | 1] ----
#pragma unroll
            for (int nh = 0; nh < 9; nh++) {
                uint32_t vb0, vb1, vb2, vb3;
                uint32_t va = vs_base + vbuf +
                    (uint32_t)((nh * 8 + lr) * VSN + srow + lt * 8) * 2;
                ldm_x4(vb0, vb1, vb2, vb3, va);
#pragma unroll
                for (int qh = 0; qh < 2; qh++) {
                    mma16(accO[qh][nh], pa[qh][0][0], pa[qh][0][1],
                          pa[qh][0][2], pa[qh][0][3], vb0, vb1);
                    mma16(accO[qh][nh], pa[qh][1][0], pa[qh][1][1],
                          pa[qh][1][2], pa[qh][1][3], vb2, vb3);
                }
            }
        }
    }

    // ---- epilogue: l lives in accO[qh][8][0/2] on t==0 lanes; broadcast ----
    float lme[2][2];
#pragma unroll
    for (int qh = 0; qh < 2; qh++) {
        lme[qh][0] = __shfl_sync(0xffffffffu, accO[qh][8][0], lane & 0x1c);
        lme[qh][1] = __shfl_sync(0xffffffffu, accO[qh][8][2], lane & 0x1c);
    }

    __syncthreads();   // all tiles done; smem reusable as f32 staging
    float* Ored = (float*)hsm;                       // [64 q][64 h]
    float* Lred = (float*)hsm + 64 * 64;             // [64 q]

    if (kw == 1) {
#pragma unroll
        for (int qh = 0; qh < 2; qh++) {
            int r = qw * 32 + qh * 16 + g;
#pragma unroll
            for (int nh = 0; nh < 8; nh++) {
                int c = nh * 8 + 2 * t;
                *reinterpret_cast<float2*>(&Ored[(size_t)r * 64 + c]) =
                    make_float2(accO[qh][nh][0], accO[qh][nh][1]);
                *reinterpret_cast<float2*>(&Ored[(size_t)(r + 8) * 64 + c]) =
                    make_float2(accO[qh][nh][2], accO[qh][nh][3]);
            }
            if (t == 0) {
                Lred[r]     = lme[qh][0];
                Lred[r + 8] = lme[qh][1];
            }
        }
    }
    __syncthreads();

    if (kw == 0) {
#pragma unroll
        for (int qh = 0; qh < 2; qh++) {
            int rl = qw * 32 + qh * 16 + g;
            float i0 = 1.f / (lme[qh][0] + Lred[rl]);
            float i1 = 1.f / (lme[qh][1] + Lred[rl + 8]);
            int r = q0 + rl;
#pragma unroll
            for (int nh = 0; nh < 8; nh++) {
                int c = nh * 8 + 2 * t;
                float2 o0 = *reinterpret_cast<const float2*>(&Ored[(size_t)rl * 64 + c]);
                float2 o1 = *reinterpret_cast<const float2*>(&Ored[(size_t)(rl + 8) * 64 + c]);
                float* o = out + ((size_t)b * T + r) * H + c;
                *reinterpret_cast<float2*>(o) =
                    make_float2((accO[qh][nh][0] + o0.x) * i0,
                                (accO[qh][nh][1] + o0.y) * i0);
                *reinterpret_cast<float2*>(o + 8 * H) =
                    make_float2((accO[qh][nh][2] + o1.x) * i1,
                                (accO[qh][nh][3] + o1.y) * i1);
            }
        }
    }
}

// ---------------------------------------------------------------------------
extern "C" void kernel_launch(void* const* d_in, const int* in_sizes, int n_in,
                              void* d_out, int out_size)
{
    const float* X  = (const float*)d_in[0];
    const float* Wq = (const float*)d_in[1];
    const float* Wk = (const float*)d_in[2];
    const float* Wv = (const float*)d_in[3];
    float* out = (float*)d_out;

    // 0) W -> fp16 transposed layout
    cvtW_kernel<<<dim3(16, 3), 256>>>(Wq, Wk, Wv);

    // 1) Fused QKV projection
    cudaFuncSetAttribute(proj_kernel,
                         cudaFuncAttributeMaxDynamicSharedMemorySize,
                         PROJ_SMEM_BYTES);
    proj_kernel<<<M_TOTAL / 128, 256, PROJ_SMEM_BYTES>>>(X);

    // 2) Causal flash attention
    cudaFuncSetAttribute(attn_kernel,
                         cudaFuncAttributeMaxDynamicSharedMemorySize,
                         ATTN_SMEM_BYTES);
    attn_kernel<<<(T / 64) * BATCH, 128, ATTN_SMEM_BYTES>>>(out);
}

// round 13
// speedup vs baseline: 1.0248x; 1.0036x over previous
#include <cuda_runtime.h>
#include <cuda_fp16.h>
#include <math.h>
#include <stdint.h>

#define BATCH 8
#define T 2048
#define E 1024
#define H 64
#define M_TOTAL (BATCH * T)   // 16384

// Scratch (fp16). Static device arrays: allocation-guard safe.
__device__ __half g_Q[M_TOTAL * H];     // [m][h], pre-scaled 0.125*log2e
__device__ __half g_K[M_TOTAL * H];     // [m][h]
__device__ __half g_Vt[BATCH * H * T];  // [b][h][t]  (transposed)
__device__ __half g_Wt[192 * E];        // [n][k]     (Wq|Wk|Wv transposed)

// ---------------------------------------------------------------------------
// helpers
// ---------------------------------------------------------------------------
__device__ __forceinline__ uint32_t pack2h(float lo, float hi) {
    __half2 h = __floats2half2_rn(lo, hi);
    return *reinterpret_cast<uint32_t*>(&h);
}
__device__ __forceinline__ uint32_t ex2h2(uint32_t x) {
    uint32_t r;
    asm("ex2.approx.f16x2 %0, %1;" : "=r"(r) : "r"(x));
    return r;
}
__device__ __forceinline__ void mma16(float* c,
                                      uint32_t a0, uint32_t a1, uint32_t a2, uint32_t a3,
                                      uint32_t b0, uint32_t b1) {
    asm("mma.sync.aligned.m16n8k16.row.col.f32.f16.f16.f32 "
        "{%0,%1,%2,%3},{%4,%5,%6,%7},{%8,%9},{%0,%1,%2,%3};"
        : "+f"(c[0]), "+f"(c[1]), "+f"(c[2]), "+f"(c[3])
        : "r"(a0), "r"(a1), "r"(a2), "r"(a3), "r"(b0), "r"(b1));
}
__device__ __forceinline__ void ldm_x4(uint32_t& r0, uint32_t& r1,
                                       uint32_t& r2, uint32_t& r3, uint32_t a) {
    asm volatile("ldmatrix.sync.aligned.m8n8.x4.shared.b16 {%0,%1,%2,%3}, [%4];"
                 : "=r"(r0), "=r"(r1), "=r"(r2), "=r"(r3) : "r"(a));
}
__device__ __forceinline__ void cpa16(uint32_t saddr, const void* gptr) {
    asm volatile("cp.async.cg.shared.global [%0], [%1], 16;"
                 :: "r"(saddr), "l"(gptr));
}
#define CP_COMMIT() asm volatile("cp.async.commit_group;")
#define CP_WAIT0()  asm volatile("cp.async.wait_group 0;")

// ---------------------------------------------------------------------------
// W pre-convert, coalesced 64x64 tile transpose via smem.
// ---------------------------------------------------------------------------
__global__ void cvtW_kernel(const float* __restrict__ Wq,
                            const float* __restrict__ Wk,
                            const float* __restrict__ Wv)
{
    __shared__ __half ts[64][72];
    const int k0 = blockIdx.x * 64;
    const int n0 = blockIdx.y * 64;
    const float* __restrict__ src =
        (blockIdx.y == 0) ? Wq : (blockIdx.y == 1) ? Wk : Wv;
    const int tid = threadIdx.x;

#pragma unroll
    for (int i = 0; i < 4; i++) {
        int idx  = tid + i * 256;
        int krow = idx >> 4;
        int c4   = (idx & 15) << 2;
        float4 v = *reinterpret_cast<const float4*>(
            src + (size_t)(k0 + krow) * H + c4);
        ts[c4 + 0][krow] = __float2half_rn(v.x);
        ts[c4 + 1][krow] = __float2half_rn(v.y);
        ts[c4 + 2][krow] = __float2half_rn(v.z);
        ts[c4 + 3][krow] = __float2half_rn(v.w);
    }
    __syncthreads();
#pragma unroll
    for (int i = 0; i < 4; i++) {
        int odx = tid + i * 256;
        int n   = odx >> 4;
        int k4  = (odx & 15) << 2;
        *reinterpret_cast<uint2*>(&g_Wt[(size_t)(n0 + n) * E + k0 + k4]) =
            *reinterpret_cast<const uint2*>(&ts[n][k4]);
    }
}

// ---------------------------------------------------------------------------
// Fused QKV projection (unchanged from R10/R12 best): fp16 MMA, X staged
// fp16, W via cp.async, ldmatrix fragments.  CTA 128x192, 8 warps 2Mx4N.
// ---------------------------------------------------------------------------
#define XSH 40
#define WSH 40
#define PROJ_SMEM_BYTES ((2 * 128 * XSH + 2 * 192 * WSH) * 2)   // 51200

__global__ __launch_bounds__(256, 1) void proj_kernel(const float* __restrict__ X)
{
    extern __shared__ __half psm[];
    __half* Xs = psm;                        // [2][128*40]
    __half* Ws = psm + 2 * 128 * XSH;        // [2][192*40]
    const uint32_t xs_base = (uint32_t)__cvta_generic_to_shared(Xs);
    const uint32_t ws_base = (uint32_t)__cvta_generic_to_shared(Ws);

    const int m0   = blockIdx.x * 128;
    const int tid  = threadIdx.x;
    const int w    = tid >> 5;
    const int lane = tid & 31;
    const int g    = lane >> 2;
    const int t    = lane & 3;
    const int wm   = (w >> 2) * 64;          // 0,64
    const int wn   = (w & 3) * 48;           // 0,48,96,144
    const int lr   = lane & 7;
    const int lt8  = ((lane >> 3) & 1) * 8;
    const int lc8  = (lane >> 4) * 8;

    float4 xa[4];
    auto loadX = [&](int k0) {
#pragma unroll
        for (int i = 0; i < 4; i++) {
            int idx = tid + i * 256;
            int row = idx >> 3;
            int c4  = (idx & 7) << 2;
            xa[i] = *reinterpret_cast<const float4*>(
                X + (size_t)(m0 + row) * E + k0 + c4);
        }
    };
    auto storeX = [&](int buf) {
#pragma unroll
        for (int i = 0; i < 4; i++) {
            int idx = tid + i * 256;
            int row = idx >> 3;
            int c4  = (idx & 7) << 2;
            *reinterpret_cast<uint2*>(&Xs[buf * 128 * XSH + row * XSH + c4]) =
                make_uint2(pack2h(xa[i].x, xa[i].y), pack2h(xa[i].z, xa[i].w));
        }
    };
    auto issueW = [&](int buf, int k0) {
#pragma unroll
        for (int i = 0; i < 3; i++) {
            int idx = tid + i * 256;
            int n   = idx >> 2;
            int c8  = (idx & 3) << 3;
            cpa16(ws_base + (uint32_t)(buf * 192 * WSH + n * WSH + c8) * 2,
                  g_Wt + (size_t)n * E + k0 + c8);
        }
        CP_COMMIT();
    };

    float acc[4][6][4] = {};

    loadX(0);
    issueW(0, 0);
    for (int ks = 0; ks < 32; ks++) {
        storeX(ks & 1);
        CP_WAIT0();
        __syncthreads();
        if (ks < 31) { loadX((ks + 1) * 32); issueW((ks + 1) & 1, (ks + 1) * 32); }

        const uint32_t xb = xs_base + (uint32_t)((ks & 1) * 128 * XSH) * 2;
        const uint32_t wb = ws_base + (uint32_t)((ks & 1) * 192 * WSH) * 2;

        uint32_t bw[6][4];
#pragma unroll
        for (int nt = 0; nt < 6; nt++) {
            uint32_t wa = wb + (uint32_t)((wn + nt * 8 + lr) * WSH + (lane >> 3) * 8) * 2;
            ldm_x4(bw[nt][0], bw[nt][1], bw[nt][2], bw[nt][3], wa);
        }
#pragma unroll
        for (int kc = 0; kc < 2; kc++) {
            uint32_t a[4][4];
#pragma unroll
            for (int mt = 0; mt < 4; mt++) {
                uint32_t xaddr = xb + (uint32_t)(
                    (wm + mt * 16 + lt8 + lr) * XSH + kc * 16 + lc8) * 2;
                ldm_x4(a[mt][0], a[mt][1], a[mt][2], a[mt][3], xaddr);
            }
#pragma unroll
            for (int nt = 0; nt < 6; nt++) {
                uint32_t b0 = bw[nt][2 * kc];
                uint32_t b1 = bw[nt][2 * kc + 1];
#pragma unroll
                for (int mt = 0; mt < 4; mt++)
                    mma16(acc[mt][nt], a[mt][0], a[mt][1], a[mt][2], a[mt][3], b0, b1);
            }
        }
    }

    const float QSCALE = 0.125f * 1.4426950408889634f;
#pragma unroll
    for (int mt = 0; mt < 4; mt++) {
        int r0 = m0 + wm + mt * 16 + g;
#pragma unroll
        for (int nt = 0; nt < 6; nt++) {
            int c = wn + nt * 8 + 2 * t;
            if (c < 64) {
                *reinterpret_cast<uint32_t*>(&g_Q[(size_t)r0 * H + c]) =
                    pack2h(acc[mt][nt][0] * QSCALE, acc[mt][nt][1] * QSCALE);
                *reinterpret_cast<uint32_t*>(&g_Q[(size_t)(r0 + 8) * H + c]) =
                    pack2h(acc[mt][nt][2] * QSCALE, acc[mt][nt][3] * QSCALE);
            } else if (c < 128) {
                int cc = c - 64;
                *reinterpret_cast<uint32_t*>(&g_K[(size_t)r0 * H + cc]) =
                    pack2h(acc[mt][nt][0], acc[mt][nt][1]);
                *reinterpret_cast<uint32_t*>(&g_K[(size_t)(r0 + 8) * H + cc]) =
                    pack2h(acc[mt][nt][2], acc[mt][nt][3]);
            } else {
                int h = c - 128;
                int bb = r0 / T, tk = r0 % T;
                __half* vb = g_Vt + (size_t)bb * H * T;
                vb[(size_t)h * T + tk]           = __float2half_rn(acc[mt][nt][0]);
                vb[(size_t)(h + 1) * T + tk]     = __float2half_rn(acc[mt][nt][1]);
                vb[(size_t)h * T + tk + 8]       = __float2half_rn(acc[mt][nt][2]);
                vb[(size_t)(h + 1) * T + tk + 8] = __float2half_rn(acc[mt][nt][3]);
            }
        }
    }
}

// ---------------------------------------------------------------------------
// Flash attention (causal), fp16 MMA, 256 threads / 8 warps.
// Warp (qw in 0..3, kw in 0..1) owns 16 q-rows x 32-key slices.
// Per-warp regs ~110 -> fits 128-reg cap of (256,2) -> 16 warps/SM.
// BK=128 per iteration (two 64-key halves); f16x2 softmax; l via V ones row.
// ---------------------------------------------------------------------------
#define KSN 72
#define VSN 136
#define VROWS 72
#define ATTN_SMEM_BYTES ((2 * 128 * KSN + 2 * VROWS * VSN) * 2)   // 76032

__global__ __launch_bounds__(256, 2) void attn_kernel(float* __restrict__ out)
{
    extern __shared__ __half hsm[];
    __half* Ks = hsm;                          // [2][128 keys x 72]
    __half* Vs = Ks + 2 * 128 * KSN;           // [2][72 h x 136]
    const uint32_t ks_base = (uint32_t)__cvta_generic_to_shared(Ks);
    const uint32_t vs_base = (uint32_t)__cvta_generic_to_shared(Vs);

    // balanced (b, qt) schedule
    const int cidx = blockIdx.x;
    int s;
    if (cidx < 108)       s = 40 + cidx;
    else if (cidx < 148)  s = cidx - 108;
    else                  s = 403 - cidx;
    const int qt = 31 - (s >> 3);
    const int b  = s & 7;
    const int q0 = qt * 64;

    const int tid  = threadIdx.x;
    const int w    = tid >> 5;
    const int lane = tid & 31;
    const int g    = lane >> 2;
    const int t    = lane & 3;
    const int qw   = w >> 1;     // 0..3 -> q rows qw*16 .. +15
    const int kw   = w & 1;      // 0..1 -> 32-key slice within each 64-key half
    const int lr   = lane & 7;
    const int lt   = lane >> 3;

    const __half* __restrict__ Qg = g_Q + ((size_t)b * T + q0) * H;
    const __half* __restrict__ Kg = g_K + (size_t)b * T * H;
    const __half* __restrict__ Vg = g_Vt + (size_t)b * H * T;

    auto issueKV = [&](int buf, int k0) {
#pragma unroll
        for (int i = 0; i < 4; i++) {          // K: 128 rows x 64 halfs
            int idx = tid + i * 256;
            int row = idx >> 3;
            int c8  = (idx & 7) << 3;
            cpa16(ks_base + (uint32_t)(buf * 128 * KSN + row * KSN + c8) * 2,
                  Kg + (size_t)(k0 + row) * H + c8);
        }
#pragma unroll
        for (int i = 0; i < 4; i++) {          // V: rows 0-63
            int idx = tid + i * 256;
            int row = idx >> 4;
            int c8  = (idx & 15) << 3;
            cpa16(vs_base + (uint32_t)(buf * VROWS * VSN + row * VSN + c8) * 2,
                  Vg + (size_t)row * T + k0 + c8);
        }
        CP_COMMIT();
    };

    const int nkt = qt / 2 + 1;
    issueKV(0, 0);

    // Init V ones-column rows (64 = 1.0, 65-71 = 0) in both buffers.
    {
        const __half one  = __float2half_rn(1.0f);
        const __half zero = __float2half_rn(0.0f);
        for (int idx = tid; idx < 2 * 8 * VSN; idx += 256) {
            int buf = idx / (8 * VSN);
            int rem = idx % (8 * VSN);
            int row = 64 + rem / VSN;
            int col = rem % VSN;
            Vs[buf * VROWS * VSN + row * VSN + col] = (row == 64) ? one : zero;
        }
    }

    // Q A-fragments for this warp's 16 q rows
    uint32_t qa[4][4];
    {
        int r = qw * 16 + g;
#pragma unroll
        for (int kc = 0; kc < 4; kc++) {
            int c = kc * 16 + 2 * t;
            qa[kc][0] = *reinterpret_cast<const uint32_t*>(&Qg[(size_t)r * H + c]);
            qa[kc][1] = *reinterpret_cast<const uint32_t*>(&Qg[(size_t)(r + 8) * H + c]);
            qa[kc][2] = *reinterpret_cast<const uint32_t*>(&Qg[(size_t)r * H + c + 8]);
            qa[kc][3] = *reinterpret_cast<const uint32_t*>(&Qg[(size_t)(r + 8) * H + c + 8]);
        }
    }

    float accO[9][4] = {};     // nh 0..7 = O cols, 8 = l column

    for (int kt = 0; kt < nkt; kt++) {
        CP_WAIT0();
        __syncthreads();
        if (kt + 1 < nkt) issueKV((kt + 1) & 1, (kt + 1) * 128);

        const uint32_t kbuf = (uint32_t)((kt & 1) * 128 * KSN) * 2;
        const uint32_t vbuf = (uint32_t)((kt & 1) * VROWS * VSN) * 2;

#pragma unroll
        for (int hb = 0; hb < 2; hb++) {
            const int kwstart = kt * 128 + hb * 64 + kw * 32;
            if (kwstart > q0 + qw * 16 + 15) continue;       // fully masked
            const bool needmask = (kwstart + 31 > q0 + qw * 16);
            const int srow = hb * 64 + kw * 32;

            // ---- S = Q @ K^T  (16q x 32k) ----
            float sv[4][4] = {};
#pragma unroll
            for (int hc = 0; hc < 2; hc++) {
#pragma unroll
                for (int nt = 0; nt < 4; nt++) {
                    uint32_t kb0, kb1, kb2, kb3;
                    uint32_t ka = ks_base + kbuf +
                        (uint32_t)((srow + nt * 8 + lr) * KSN + hc * 32 + lt * 8) * 2;
                    ldm_x4(kb0, kb1, kb2, kb3, ka);
                    mma16(sv[nt], qa[2*hc][0], qa[2*hc][1],
                          qa[2*hc][2], qa[2*hc][3], kb0, kb1);
                    mma16(sv[nt], qa[2*hc+1][0], qa[2*hc+1][1],
                          qa[2*hc+1][2], qa[2*hc+1][3], kb2, kb3);
                }
            }

            // causal mask (global indices)
            if (needmask) {
                int r0 = q0 + qw * 16 + g;
                int r1 = r0 + 8;
#pragma unroll
                for (int nt = 0; nt < 4; nt++) {
                    int cc = kwstart + nt * 8 + 2 * t;
                    if (cc     > r0) sv[nt][0] = -1e30f;
                    if (cc + 1 > r0) sv[nt][1] = -1e30f;
                    if (cc     > r1) sv[nt][2] = -1e30f;
                    if (cc + 1 > r1) sv[nt][3] = -1e30f;
                }
            }

            // ---- P = 2^S (f16x2) -> P A-fragment ----
            uint32_t pa[2][4];
#pragma unroll
            for (int nt = 0; nt < 4; nt++) {
                pa[nt >> 1][(nt & 1) * 2 + 0] =
                    ex2h2(pack2h(sv[nt][0], sv[nt][1]));
                pa[nt >> 1][(nt & 1) * 2 + 1] =
                    ex2h2(pack2h(sv[nt][2], sv[nt][3]));
            }

            // ---- [O | l] += P @ [V | 1] ----
#pragma unroll
            for (int nh = 0; nh < 9; nh++) {
                uint32_t vb0, vb1, vb2, vb3;
                uint32_t va = vs_base + vbuf +
                    (uint32_t)((nh * 8 + lr) * VSN + srow + lt * 8) * 2;
                ldm_x4(vb0, vb1, vb2, vb3, va);
                mma16(accO[nh], pa[0][0], pa[0][1], pa[0][2], pa[0][3], vb0, vb1);
                mma16(accO[nh], pa[1][0], pa[1][1], pa[1][2], pa[1][3], vb2, vb3);
            }
        }
    }

    // ---- epilogue: l from accO[8]; reduce across kw pair; store ----
    float lme0 = __shfl_sync(0xffffffffu, accO[8][0], lane & 0x1c);
    float lme1 = __shfl_sync(0xffffffffu, accO[8][2], lane & 0x1c);

    __syncthreads();   // all tiles done; smem reusable as f32 staging
    float* Ored = (float*)hsm;                       // [64 q][64 h]
    float* Lred = (float*)hsm + 64 * 64;             // [64 q]

    if (kw == 1) {
        int r = qw * 16 + g;
#pragma unroll
        for (int nh = 0; nh < 8; nh++) {
            int c = nh * 8 + 2 * t;
            *reinterpret_cast<float2*>(&Ored[(size_t)r * 64 + c]) =
                make_float2(accO[nh][0], accO[nh][1]);
            *reinterpret_cast<float2*>(&Ored[(size_t)(r + 8) * 64 + c]) =
                make_float2(accO[nh][2], accO[nh][3]);
        }
        if (t == 0) {
            Lred[r]     = lme0;
            Lred[r + 8] = lme1;
        }
    }
    __syncthreads();

    if (kw == 0) {
        int rl = qw * 16 + g;
        float i0 = 1.f / (lme0 + Lred[rl]);
        float i1 = 1.f / (lme1 + Lred[rl + 8]);
        int r = q0 + rl;
#pragma unroll
        for (int nh = 0; nh < 8; nh++) {
            int c = nh * 8 + 2 * t;
            float2 o0 = *reinterpret_cast<const float2*>(&Ored[(size_t)rl * 64 + c]);
            float2 o1 = *reinterpret_cast<const float2*>(&Ored[(size_t)(rl + 8) * 64 + c]);
            float* o = out + ((size_t)b * T + r) * H + c;
            *reinterpret_cast<float2*>(o) =
                make_float2((accO[nh][0] + o0.x) * i0,
                            (accO[nh][1] + o0.y) * i0);
            *reinterpret_cast<float2*>(o + 8 * H) =
                make_float2((accO[nh][2] + o1.x) * i1,
                            (accO[nh][3] + o1.y) * i1);
        }
    }
}

// ---------------------------------------------------------------------------
extern "C" void kernel_launch(void* const* d_in, const int* in_sizes, int n_in,
                              void* d_out, int out_size)
{
    const float* X  = (const float*)d_in[0];
    const float* Wq = (const float*)d_in[1];
    const float* Wk = (const float*)d_in[2];
    const float* Wv = (const float*)d_in[3];
    float* out = (float*)d_out;

    // 0) W -> fp16 transposed layout
    cvtW_kernel<<<dim3(16, 3), 256>>>(Wq, Wk, Wv);

    // 1) Fused QKV projection
    cudaFuncSetAttribute(proj_kernel,
                         cudaFuncAttributeMaxDynamicSharedMemorySize,
                         PROJ_SMEM_BYTES);
    proj_kernel<<<M_TOTAL / 128, 256, PROJ_SMEM_BYTES>>>(X);

    // 2) Causal flash attention (256 threads, 16 warps/SM)
    cudaFuncSetAttribute(attn_kernel,
                         cudaFuncAttributeMaxDynamicSharedMemorySize,
                         ATTN_SMEM_BYTES);
    attn_kernel<<<(T / 64) * BATCH, 256, ATTN_SMEM_BYTES>>>(out);
}